// round 13
// baseline (speedup 1.0000x reference)
#include <cuda_runtime.h>
#include <cuda_bf16.h>
#include <cuda_fp16.h>
#include <cstdint>
#include <cstring>

// GRU_90821378441798 — HMMA bf16 GEMM (A via ldmatrix.trans from [c][n] tile)
// + warp-local minGRU scan with vectorized writeback.
// R13: FEATS transposed -> scan/prologue write STS.128 rows; single-inst bf16x2 cvt.

#define FEATS_T  0              // 128 rows (channel) x 128B (64 bf16 n), 16B units XOR-swizzled
#define HGT_OFF  16384          // 128 rows (channel) x 272B: [64 hid | 64 gat | pad] halfs
#define HGT_STRIDE 272
#define XR_OFF   51200          // 64 floats
#define WOUT_OFF 51456          // 128 floats
#define SMEM_TOTAL 51968

__device__ float d_BaseT[4 * 128 * 64];                    // [b][c][n] = (xs@W1[1:,:]+b1)^T
__device__ __align__(16) uint4 d_Wpack4[2 * 4 * 32 * 32];  // [layer][kp][nt][lane]: xy=kt2kp, zw=kt2kp+1

static __device__ __forceinline__ uint32_t h2u(__half2 v) {
    uint32_t r; memcpy(&r, &v, 4); return r;
}
static __device__ __forceinline__ uint32_t bf2(float lo, float hi) {   // pack: lo half = lo
    uint32_t r; asm("cvt.rn.bf16x2.f32 %0, %1, %2;" : "=r"(r) : "f"(hi), "f"(lo)); return r;
}
static __device__ __forceinline__ uint32_t smem_u32(const void* p) {
    uint32_t a;
    asm("{ .reg .u64 t; cvta.to.shared.u64 t, %1; cvt.u32.u64 %0, t; }" : "=r"(a) : "l"(p));
    return a;
}
static __device__ __forceinline__ float tanh_ap(float x) {
    float r; asm("tanh.approx.f32 %0, %1;" : "=f"(r) : "f"(x)); return r;
}
static __device__ __forceinline__ float sigmoid_f(float x) {
    return fmaf(0.5f, tanh_ap(0.5f * x), 0.5f);
}
static __device__ __forceinline__ uint32_t prmt(uint32_t a, uint32_t b, uint32_t sel) {
    uint32_t d; asm("prmt.b32 %0, %1, %2, %3;" : "=r"(d) : "r"(a), "r"(b), "r"(sel)); return d;
}
static __device__ __forceinline__ void ldsm4t(uint32_t* r, uint32_t addr) {
    asm volatile("ldmatrix.sync.aligned.m8n8.x4.trans.shared.b16 {%0,%1,%2,%3}, [%4];"
                 : "=r"(r[0]), "=r"(r[1]), "=r"(r[2]), "=r"(r[3]) : "r"(addr));
}
static __device__ __forceinline__ void mma16816(float* c, const uint32_t* a, uint32_t b0, uint32_t b1) {
    asm volatile("mma.sync.aligned.m16n8k16.row.col.f32.bf16.bf16.f32 "
                 "{%0,%1,%2,%3},{%4,%5,%6,%7},{%8,%9},{%0,%1,%2,%3};"
                 : "+f"(c[0]), "+f"(c[1]), "+f"(c[2]), "+f"(c[3])
                 : "r"(a[0]), "r"(a[1]), "r"(a[2]), "r"(a[3]), "r"(b0), "r"(b1));
}
static __device__ __forceinline__ uint32_t bfpack(float a, float b) {
    return ((uint32_t)__bfloat16_as_ushort(__float2bfloat16(b)) << 16)
         | (uint32_t)__bfloat16_as_ushort(__float2bfloat16(a));
}

// ---------- merged prep kernel ----------
__global__ void prep_kernel(const float* __restrict__ xs,
                            const float* __restrict__ W1,
                            const float* __restrict__ b1,
                            const float* __restrict__ Wg) {
    if (blockIdx.x < 32) {
        int idx = blockIdx.x * 256 + threadIdx.x;        // 8192
        int lane = idx & 31;
        int nt = (idx >> 5) & 31;
        int kp = (idx >> 10) & 3;
        int layer = idx >> 12;
        int n = nt * 8 + (lane >> 2);
        const float* Wl = Wg + layer * 32768;
        uint4 v;
        {
            int k0 = (2 * kp) * 16 + 2 * (lane & 3);
            v.x = bfpack(Wl[k0 * 256 + n], Wl[(k0 + 1) * 256 + n]);
            v.y = bfpack(Wl[(k0 + 8) * 256 + n], Wl[(k0 + 9) * 256 + n]);
        }
        {
            int k0 = (2 * kp + 1) * 16 + 2 * (lane & 3);
            v.z = bfpack(Wl[k0 * 256 + n], Wl[(k0 + 1) * 256 + n]);
            v.w = bfpack(Wl[(k0 + 8) * 256 + n], Wl[(k0 + 9) * 256 + n]);
        }
        d_Wpack4[idx] = v;
    } else {
        int row = (blockIdx.x - 32) * 2 + (threadIdx.x >> 7);   // b*64+n, 0..255
        int c = threadIdx.x & 127;
        float s = b1[c];
        const float* xr = xs + row * 15;
#pragma unroll
        for (int f = 0; f < 15; f++) s = fmaf(xr[f], W1[(f + 1) * 128 + c], s);
        d_BaseT[(row >> 6) * 8192 + c * 64 + (row & 63)] = s;   // transposed
    }
}

// ---------- main kernel ----------
__global__ void __launch_bounds__(128, 4)
gru_mma_kernel(const float* __restrict__ x,
               const float* __restrict__ W1,
               const float* __restrict__ W_out,
               const float* __restrict__ b_out,
               float* __restrict__ out) {
    extern __shared__ __align__(128) char sm[];
    const uint32_t sbase = smem_u32(sm);

    const int tid = threadIdx.x;
    const int w = tid >> 5;
    const int t = tid & 31;
    const int b = blockIdx.x >> 10;
    const int l = blockIdx.x & 1023;

    float* xr = (float*)(sm + XR_OFF);
    float* wouts = (float*)(sm + WOUT_OFF);

    if (tid < 64) xr[tid] = x[(b * 64 + tid) * 1024 + l];
    wouts[tid] = W_out[tid];
    __syncthreads();

    const int c = w * 32 + t;                   // this thread's channel
    char* frow = sm + FEATS_T + c * 128;
    char* crow = sm + HGT_OFF + c * HGT_STRIDE;

    // ---- layer-0 feats: thread c fills its own FEATS_T row ----
    {
        const float w1c = W1[c];
        const float4* bt = (const float4*)(d_BaseT + b * 8192 + c * 64);
        const float4* x4 = (const float4*)xr;
#pragma unroll
        for (int ch = 0; ch < 8; ch++) {
            float4 b0 = bt[2 * ch], b1v = bt[2 * ch + 1];
            float4 xa = x4[2 * ch], xb = x4[2 * ch + 1];
            uint4 u;
            u.x = bf2(fmaxf(fmaf(xa.x, w1c, b0.x), 0.f), fmaxf(fmaf(xa.y, w1c, b0.y), 0.f));
            u.y = bf2(fmaxf(fmaf(xa.z, w1c, b0.z), 0.f), fmaxf(fmaf(xa.w, w1c, b0.w), 0.f));
            u.z = bf2(fmaxf(fmaf(xb.x, w1c, b1v.x), 0.f), fmaxf(fmaf(xb.y, w1c, b1v.y), 0.f));
            u.w = bf2(fmaxf(fmaf(xb.z, w1c, b1v.z), 0.f), fmaxf(fmaf(xb.w, w1c, b1v.w), 0.f));
            *(uint4*)(frow + ((ch ^ (c & 7)) << 4)) = u;
        }
    }
    __syncthreads();

    const uint32_t psel = ((t >> 2) & 1) ? 0x3276u : 0x5410u;
    const int cqb0 = ((t >> 4) & 1) * 8 + (t & 7);    // kt-row base within fragment
    const uint32_t ub = (t >> 3) & 1;

#pragma unroll 1
    for (int layer = 0; layer < 2; layer++) {
        // ---- GEMM: pass 0 = hid cols [32w,+32), pass 1 = gate cols [128+32w,+32) ----
#pragma unroll 1
        for (int p = 0; p < 2; p++) {
            float acc[64];
#pragma unroll
            for (int i = 0; i < 64; i++) acc[i] = 0.0f;

            const uint4* wlp = d_Wpack4 + layer * 4096 + (p * 16 + 4 * w) * 32 + t;

            uint4 bw[2][4];
#pragma unroll
            for (int j = 0; j < 4; j++) bw[0][j] = wlp[j * 32];

#pragma unroll
            for (int kp = 0; kp < 4; kp++) {
                const int cur = kp & 1, nxt = cur ^ 1;
                const int cq0 = 32 * kp + cqb0;           // kt = 2kp
                const int cq1 = cq0 + 16;                 // kt = 2kp+1
                uint32_t Ah[16];

#pragma unroll
                for (int mt = 0; mt < 4; mt++) {          // kt = 2kp
                    uint32_t unit = 2 * mt + ub;
                    ldsm4t(Ah + 4 * mt, sbase + FEATS_T + cq0 * 128 + ((unit ^ (cq0 & 7)) << 4));
                }
                if (kp < 3) {
#pragma unroll
                    for (int j = 0; j < 4; j++) bw[nxt][j] = wlp[(kp + 1) * 1024 + j * 32];
                }
#pragma unroll
                for (int j = 0; j < 4; j++)
#pragma unroll
                    for (int mt = 0; mt < 4; mt++)
                        mma16816(acc + (j * 4 + mt) * 4, Ah + 4 * mt, bw[cur][j].x, bw[cur][j].y);

#pragma unroll
                for (int mt = 0; mt < 4; mt++) {          // kt = 2kp+1
                    uint32_t unit = 2 * mt + ub;
                    ldsm4t(Ah + 4 * mt, sbase + FEATS_T + cq1 * 128 + ((unit ^ (cq1 & 7)) << 4));
                }
#pragma unroll
                for (int j = 0; j < 4; j++)
#pragma unroll
                    for (int mt = 0; mt < 4; mt++)
                        mma16816(acc + (j * 4 + mt) * 4, Ah + 4 * mt, bw[cur][j].z, bw[cur][j].w);
            }

            // ---- store hg fragments transposed into HGT: row = channel ----
#pragma unroll
            for (int j = 0; j < 4; j++) {
                int cc = (p * 16 + 4 * w + j) * 8 + 2 * (t & 3) + ((t >> 2) & 1);
                char* rowp = sm + HGT_OFF + (cc & 127) * HGT_STRIDE + ((cc >> 7) << 7);
#pragma unroll
                for (int mt = 0; mt < 4; mt++) {
                    int np = 16 * mt + ((t >> 2) & 6);
                    const float* cp = acc + (j * 4 + mt) * 4;
                    uint32_t h01 = h2u(__floats2half2_rn(cp[0], cp[1]));
                    uint32_t h23 = h2u(__floats2half2_rn(cp[2], cp[3]));
                    uint32_t v01 = __shfl_xor_sync(0xffffffffu, h01, 4);
                    uint32_t v23 = __shfl_xor_sync(0xffffffffu, h23, 4);
                    *(uint32_t*)(rowp + np * 2) = prmt(h01, v01, psel);
                    *(uint32_t*)(rowp + np * 2 + 16) = prmt(h23, v23, psel);
                }
            }
        }

        // layer 0: CTA barrier (scan overwrites FEATS_T that other warps' ldsm read).
        // layer 1: warp-local only.
        if (layer == 0) __syncthreads();
        else            __syncwarp();

        // ---- minGRU scan over n for channel c (warp-local data) ----
        {
            float h = 0.0f;
#pragma unroll
            for (int ch = 0; ch < 8; ch++) {
                uint4 hv = *(const uint4*)(crow + ch * 16);
                uint4 gv = *(const uint4*)(crow + 128 + ch * 16);
                uint32_t hw[4] = {hv.x, hv.y, hv.z, hv.w};
                uint32_t gw[4] = {gv.x, gv.y, gv.z, gv.w};
                uint32_t fpk[4];
#pragma unroll
                for (int wi = 0; wi < 4; wi++) {
                    float2 hf = __half22float2(*(const __half2*)&hw[wi]);
                    float2 gf = __half22float2(*(const __half2*)&gw[wi]);
                    int n0 = ch * 8 + 2 * wi;
                    float h0;
                    {
                        float z = sigmoid_f(gf.x);
                        float gg = (hf.x >= 0.0f) ? (hf.x + 0.5f) : sigmoid_f(hf.x);
                        float v = z * gg;
                        h = (n0 == 0) ? v : fmaf(1.0f - z, h, v);
                        h0 = h;
                    }
                    {
                        float z = sigmoid_f(gf.y);
                        float gg = (hf.y >= 0.0f) ? (hf.y + 0.5f) : sigmoid_f(hf.y);
                        float v = z * gg;
                        h = fmaf(1.0f - z, h, v);
                    }
                    if (layer == 0) fpk[wi] = bf2(h0, h);
                    else            fpk[wi] = h2u(__floats2half2_rn(h0, h));
                }
                if (layer == 0) {
                    *(uint4*)(frow + ((ch ^ (c & 7)) << 4)) = make_uint4(fpk[0], fpk[1], fpk[2], fpk[3]);
                } else {
                    *(uint4*)(crow + ch * 16) = make_uint4(fpk[0], fpk[1], fpk[2], fpk[3]);
                }
            }
        }
        __syncthreads();
    }

    // ---- output: out[b,n,l] = sum_c h[c][n]*Wout[c] + b_out + x ----
    if (tid < 64) {
        const int n = tid;
        const char* hb = sm + HGT_OFF + n * 2;
        float s0 = 0.f, s1 = 0.f, s2 = 0.f, s3 = 0.f;
#pragma unroll
        for (int q = 0; q < 128; q += 4) {
            s0 = fmaf(__half2float(*(const __half*)(hb + (q + 0) * HGT_STRIDE)), wouts[q + 0], s0);
            s1 = fmaf(__half2float(*(const __half*)(hb + (q + 1) * HGT_STRIDE)), wouts[q + 1], s1);
            s2 = fmaf(__half2float(*(const __half*)(hb + (q + 2) * HGT_STRIDE)), wouts[q + 2], s2);
            s3 = fmaf(__half2float(*(const __half*)(hb + (q + 3) * HGT_STRIDE)), wouts[q + 3], s3);
        }
        out[(b * 64 + n) * 1024 + l] = (s0 + s1) + (s2 + s3) + b_out[0] + xr[n];
    }
}

extern "C" void kernel_launch(void* const* d_in, const int* in_sizes, int n_in,
                              void* d_out, int out_size) {
    const float* xs = (const float*)d_in[0];
    const float* x  = (const float*)d_in[1];
    const float* W1 = (const float*)d_in[2];
    const float* b1 = (const float*)d_in[3];
    const float* Wg = (const float*)d_in[4];
    const float* Wo = (const float*)d_in[5];
    const float* bo = (const float*)d_in[6];
    float* out = (float*)d_out;

    cudaFuncSetAttribute(gru_mma_kernel, cudaFuncAttributeMaxDynamicSharedMemorySize, SMEM_TOTAL);
    prep_kernel<<<160, 256>>>(xs, W1, b1, Wg);
    gru_mma_kernel<<<4096, 128, SMEM_TOTAL>>>(x, W1, Wo, bo, out);
}

// round 14
// speedup vs baseline: 1.0891x; 1.0891x over previous
#include <cuda_runtime.h>
#include <cuda_bf16.h>
#include <cuda_fp16.h>
#include <cstdint>
#include <cstring>

// GRU_90821378441798 — HMMA bf16 GEMM + warp-local minGRU scan.
// R14: R12 base; layer-0 scan compute hoisted BEFORE the CTA barrier (only the
//      FEATS writeback stays serialized). Non-trans ldsm (R13's trans regressed).

#define FEATS_HI 0              // 64 rows x 256B swizzled bf16
#define HGT_OFF  16384          // 128 rows (channel) x 272B: [64 hid | 64 gat | pad]
#define HGT_STRIDE 272
#define XR_OFF   51200
#define W1S_OFF  51456
#define WOUT_OFF 51968
#define SMEM_TOTAL 52480

__device__ float d_Base[4 * 64 * 128];                     // xs@W1[1:,:]+b1
__device__ __align__(16) uint4 d_Wpack4[2 * 4 * 32 * 32];  // [layer][kp][nt][lane]: xy=kt2kp, zw=kt2kp+1

static __device__ __forceinline__ uint32_t h2u(__half2 v) {
    uint32_t r; memcpy(&r, &v, 4); return r;
}
static __device__ __forceinline__ uint32_t bf2(float lo, float hi) {   // packed bf16x2, low half = lo
    uint32_t r; asm("cvt.rn.bf16x2.f32 %0, %1, %2;" : "=r"(r) : "f"(hi), "f"(lo)); return r;
}
static __device__ __forceinline__ uint32_t smem_u32(const void* p) {
    uint32_t a;
    asm("{ .reg .u64 t; cvta.to.shared.u64 t, %1; cvt.u32.u64 %0, t; }" : "=r"(a) : "l"(p));
    return a;
}
static __device__ __forceinline__ float tanh_ap(float x) {
    float r; asm("tanh.approx.f32 %0, %1;" : "=f"(r) : "f"(x)); return r;
}
static __device__ __forceinline__ float sigmoid_f(float x) {
    return fmaf(0.5f, tanh_ap(0.5f * x), 0.5f);
}
static __device__ __forceinline__ uint32_t prmt(uint32_t a, uint32_t b, uint32_t sel) {
    uint32_t d; asm("prmt.b32 %0, %1, %2, %3;" : "=r"(d) : "r"(a), "r"(b), "r"(sel)); return d;
}
static __device__ __forceinline__ void ldsm4(uint32_t* r, uint32_t addr) {
    asm volatile("ldmatrix.sync.aligned.m8n8.x4.shared.b16 {%0,%1,%2,%3}, [%4];"
                 : "=r"(r[0]), "=r"(r[1]), "=r"(r[2]), "=r"(r[3]) : "r"(addr));
}
static __device__ __forceinline__ void mma16816(float* c, const uint32_t* a, uint32_t b0, uint32_t b1) {
    asm volatile("mma.sync.aligned.m16n8k16.row.col.f32.bf16.bf16.f32 "
                 "{%0,%1,%2,%3},{%4,%5,%6,%7},{%8,%9},{%0,%1,%2,%3};"
                 : "+f"(c[0]), "+f"(c[1]), "+f"(c[2]), "+f"(c[3])
                 : "r"(a[0]), "r"(a[1]), "r"(a[2]), "r"(a[3]), "r"(b0), "r"(b1));
}
static __device__ __forceinline__ uint32_t bfpack(float a, float b) {
    return ((uint32_t)__bfloat16_as_ushort(__float2bfloat16(b)) << 16)
         | (uint32_t)__bfloat16_as_ushort(__float2bfloat16(a));
}

// ---------- merged prep kernel ----------
__global__ void prep_kernel(const float* __restrict__ xs,
                            const float* __restrict__ W1,
                            const float* __restrict__ b1,
                            const float* __restrict__ Wg) {
    if (blockIdx.x < 32) {
        int idx = blockIdx.x * 256 + threadIdx.x;        // 8192
        int lane = idx & 31;
        int nt = (idx >> 5) & 31;
        int kp = (idx >> 10) & 3;
        int layer = idx >> 12;
        int n = nt * 8 + (lane >> 2);
        const float* Wl = Wg + layer * 32768;
        uint4 v;
        {
            int k0 = (2 * kp) * 16 + 2 * (lane & 3);
            v.x = bfpack(Wl[k0 * 256 + n], Wl[(k0 + 1) * 256 + n]);
            v.y = bfpack(Wl[(k0 + 8) * 256 + n], Wl[(k0 + 9) * 256 + n]);
        }
        {
            int k0 = (2 * kp + 1) * 16 + 2 * (lane & 3);
            v.z = bfpack(Wl[k0 * 256 + n], Wl[(k0 + 1) * 256 + n]);
            v.w = bfpack(Wl[(k0 + 8) * 256 + n], Wl[(k0 + 9) * 256 + n]);
        }
        d_Wpack4[idx] = v;
    } else {
        int row = (blockIdx.x - 32) * 2 + (threadIdx.x >> 7);   // 0..255
        int c = threadIdx.x & 127;
        float s = b1[c];
        const float* xr = xs + row * 15;
#pragma unroll
        for (int f = 0; f < 15; f++) s = fmaf(xr[f], W1[(f + 1) * 128 + c], s);
        d_Base[row * 128 + c] = s;
    }
}

// ---------- main kernel ----------
__global__ void __launch_bounds__(128, 4)
gru_mma_kernel(const float* __restrict__ x,
               const float* __restrict__ W1,
               const float* __restrict__ W_out,
               const float* __restrict__ b_out,
               float* __restrict__ out) {
    extern __shared__ __align__(128) char sm[];
    const uint32_t sbase = smem_u32(sm);

    const int tid = threadIdx.x;
    const int w = tid >> 5;
    const int t = tid & 31;
    const int b = blockIdx.x >> 10;
    const int l = blockIdx.x & 1023;

    float* xr = (float*)(sm + XR_OFF);
    float* w1s = (float*)(sm + W1S_OFF);
    float* wouts = (float*)(sm + WOUT_OFF);

    if (tid < 64) xr[tid] = x[(b * 64 + tid) * 1024 + l];
    w1s[tid] = W1[tid];
    wouts[tid] = W_out[tid];
    __syncthreads();

    // ---- layer-0 feats -> swizzled bf16 A tile ----
    {
        const float4* base4 = (const float4*)d_Base;
        const float4* w14 = (const float4*)w1s;
#pragma unroll
        for (int it = 0; it < 16; it++) {
            int i = tid + 128 * it;
            int r = i >> 5, j = i & 31;
            float4 bs = base4[(b * 64 + r) * 32 + j];
            float4 wv = w14[j];
            float xv = xr[r];
            float v0 = fmaxf(fmaf(xv, wv.x, bs.x), 0.0f);
            float v1 = fmaxf(fmaf(xv, wv.y, bs.y), 0.0f);
            float v2 = fmaxf(fmaf(xv, wv.z, bs.z), 0.0f);
            float v3 = fmaxf(fmaf(xv, wv.w, bs.w), 0.0f);
            int off = r * 256 + ((((j >> 1) ^ (r & 7))) << 4) + 8 * (j & 1);
            *(uint2*)(sm + FEATS_HI + off) = make_uint2(bfpack(v0, v1), bfpack(v2, v3));
        }
    }
    __syncthreads();

    const uint32_t psel = ((t >> 2) & 1) ? 0x3276u : 0x5410u;
    const int c = w * 32 + t;               // this thread's scan channel
    char* crow = sm + HGT_OFF + c * HGT_STRIDE;

#pragma unroll 1
    for (int layer = 0; layer < 2; layer++) {
        // ---- GEMM: pass 0 = hid cols [32w,32w+32), pass 1 = gate cols [128+32w, +32) ----
#pragma unroll 1
        for (int p = 0; p < 2; p++) {
            float acc[64];
#pragma unroll
            for (int i = 0; i < 64; i++) acc[i] = 0.0f;

            const uint4* wlp = d_Wpack4 + layer * 4096 + (p * 16 + 4 * w) * 32 + t;

            uint4 bw[2][4];
#pragma unroll
            for (int j = 0; j < 4; j++) bw[0][j] = wlp[j * 32];

#pragma unroll
            for (int kp = 0; kp < 4; kp++) {
                const int cur = kp & 1, nxt = cur ^ 1;

                uint32_t Ah[16];
#pragma unroll
                for (int mt = 0; mt < 4; mt++) {        // kt = 2*kp
                    int row = 16 * mt + (t & 7) + ((t >> 3) & 1) * 8;
                    uint32_t unit = (uint32_t)(4 * kp + (t >> 4));
                    uint32_t off = (uint32_t)(row * 256) + ((unit ^ (uint32_t)(row & 7)) << 4);
                    ldsm4(Ah + 4 * mt, sbase + FEATS_HI + off);
                }
                if (kp < 3) {
#pragma unroll
                    for (int j = 0; j < 4; j++) bw[nxt][j] = wlp[(kp + 1) * 1024 + j * 32];
                }
#pragma unroll
                for (int j = 0; j < 4; j++)
#pragma unroll
                    for (int mt = 0; mt < 4; mt++)
                        mma16816(acc + (j * 4 + mt) * 4, Ah + 4 * mt, bw[cur][j].x, bw[cur][j].y);

#pragma unroll
                for (int mt = 0; mt < 4; mt++) {        // kt = 2*kp+1
                    int row = 16 * mt + (t & 7) + ((t >> 3) & 1) * 8;
                    uint32_t unit = (uint32_t)(4 * kp + 2 + (t >> 4));
                    uint32_t off = (uint32_t)(row * 256) + ((unit ^ (uint32_t)(row & 7)) << 4);
                    ldsm4(Ah + 4 * mt, sbase + FEATS_HI + off);
                }
#pragma unroll
                for (int j = 0; j < 4; j++)
#pragma unroll
                    for (int mt = 0; mt < 4; mt++)
                        mma16816(acc + (j * 4 + mt) * 4, Ah + 4 * mt, bw[cur][j].z, bw[cur][j].w);
            }

            // ---- store hg fragments transposed: row = channel ----
#pragma unroll
            for (int j = 0; j < 4; j++) {
                int cc = (p * 16 + 4 * w + j) * 8 + 2 * (t & 3) + ((t >> 2) & 1);
                char* rowp = sm + HGT_OFF + (cc & 127) * HGT_STRIDE + ((cc >> 7) << 7);
#pragma unroll
                for (int mt = 0; mt < 4; mt++) {
                    int np = 16 * mt + ((t >> 2) & 6);
                    const float* cp = acc + (j * 4 + mt) * 4;
                    uint32_t h01 = h2u(__floats2half2_rn(cp[0], cp[1]));
                    uint32_t h23 = h2u(__floats2half2_rn(cp[2], cp[3]));
                    uint32_t v01 = __shfl_xor_sync(0xffffffffu, h01, 4);
                    uint32_t v23 = __shfl_xor_sync(0xffffffffu, h23, 4);
                    *(uint32_t*)(rowp + np * 2) = prmt(h01, v01, psel);
                    *(uint32_t*)(rowp + np * 2 + 16) = prmt(h23, v23, psel);
                }
            }
        }

        // ---- scan compute (warp-local HGT reads only; no CTA barrier needed) ----
        __syncwarp();
        if (layer == 0) {
            uint32_t pk[32];                 // packed bf16x2 h pairs (n, n+1)
            {
                float h = 0.0f;
#pragma unroll
                for (int ch = 0; ch < 8; ch++) {
                    uint4 hv = *(const uint4*)(crow + ch * 16);
                    uint4 gv = *(const uint4*)(crow + 128 + ch * 16);
                    uint32_t hw[4] = {hv.x, hv.y, hv.z, hv.w};
                    uint32_t gw[4] = {gv.x, gv.y, gv.z, gv.w};
#pragma unroll
                    for (int wi = 0; wi < 4; wi++) {
                        float2 hf = __half22float2(*(const __half2*)&hw[wi]);
                        float2 gf = __half22float2(*(const __half2*)&gw[wi]);
                        int n0 = ch * 8 + 2 * wi;
                        float h0;
                        {
                            float z = sigmoid_f(gf.x);
                            float gg = (hf.x >= 0.0f) ? (hf.x + 0.5f) : sigmoid_f(hf.x);
                            float v = z * gg;
                            h = (n0 == 0) ? v : fmaf(1.0f - z, h, v);
                            h0 = h;
                        }
                        {
                            float z = sigmoid_f(gf.y);
                            float gg = (hf.y >= 0.0f) ? (hf.y + 0.5f) : sigmoid_f(hf.y);
                            float v = z * gg;
                            h = fmaf(1.0f - z, h, v);
                        }
                        pk[ch * 4 + wi] = bf2(h0, h);
                    }
                }
            }
            __syncthreads();     // all warps' layer-0 ldsm complete; FEATS may be overwritten
            // writeback next-layer feats (scattered bf16, short serialized region)
#pragma unroll
            for (int m = 0; m < 32; m++) {
                int n0 = 2 * m, n1 = 2 * m + 1;
                int off0 = n0 * 256 + ((((c >> 3) ^ (n0 & 7))) << 4) + ((2 * c) & 14);
                int off1 = n1 * 256 + ((((c >> 3) ^ (n1 & 7))) << 4) + ((2 * c) & 14);
                uint32_t v = pk[m];
                *(unsigned short*)(sm + FEATS_HI + off0) = (unsigned short)(v & 0xffffu);
                *(unsigned short*)(sm + FEATS_HI + off1) = (unsigned short)(v >> 16);
            }
        } else {
            float h = 0.0f;
#pragma unroll
            for (int ch = 0; ch < 8; ch++) {
                uint4 hv = *(const uint4*)(crow + ch * 16);
                uint4 gv = *(const uint4*)(crow + 128 + ch * 16);
                uint32_t hw[4] = {hv.x, hv.y, hv.z, hv.w};
                uint32_t gw[4] = {gv.x, gv.y, gv.z, gv.w};
                uint32_t fpk[4];
#pragma unroll
                for (int wi = 0; wi < 4; wi++) {
                    float2 hf = __half22float2(*(const __half2*)&hw[wi]);
                    float2 gf = __half22float2(*(const __half2*)&gw[wi]);
                    int n0 = ch * 8 + 2 * wi;
                    float h0;
                    {
                        float z = sigmoid_f(gf.x);
                        float gg = (hf.x >= 0.0f) ? (hf.x + 0.5f) : sigmoid_f(hf.x);
                        float v = z * gg;
                        h = (n0 == 0) ? v : fmaf(1.0f - z, h, v);
                        h0 = h;
                    }
                    {
                        float z = sigmoid_f(gf.y);
                        float gg = (hf.y >= 0.0f) ? (hf.y + 0.5f) : sigmoid_f(hf.y);
                        float v = z * gg;
                        h = fmaf(1.0f - z, h, v);
                    }
                    fpk[wi] = h2u(__floats2half2_rn(h0, h));
                }
                *(uint4*)(crow + ch * 16) = make_uint4(fpk[0], fpk[1], fpk[2], fpk[3]);
            }
        }
        __syncthreads();    // layer0: FEATS ready for next GEMM; layer1: HGT ready for epilogue
    }

    // ---- output: out[b,n,l] = sum_c h[c][n]*Wout[c] + b_out + x ----
    if (tid < 64) {
        const int n = tid;
        const char* hb = sm + HGT_OFF + n * 2;
        float s0 = 0.f, s1 = 0.f, s2 = 0.f, s3 = 0.f;
#pragma unroll
        for (int q = 0; q < 128; q += 4) {
            s0 = fmaf(__half2float(*(const __half*)(hb + (q + 0) * HGT_STRIDE)), wouts[q + 0], s0);
            s1 = fmaf(__half2float(*(const __half*)(hb + (q + 1) * HGT_STRIDE)), wouts[q + 1], s1);
            s2 = fmaf(__half2float(*(const __half*)(hb + (q + 2) * HGT_STRIDE)), wouts[q + 2], s2);
            s3 = fmaf(__half2float(*(const __half*)(hb + (q + 3) * HGT_STRIDE)), wouts[q + 3], s3);
        }
        out[(b * 64 + n) * 1024 + l] = (s0 + s1) + (s2 + s3) + b_out[0] + xr[n];
    }
}

extern "C" void kernel_launch(void* const* d_in, const int* in_sizes, int n_in,
                              void* d_out, int out_size) {
    const float* xs = (const float*)d_in[0];
    const float* x  = (const float*)d_in[1];
    const float* W1 = (const float*)d_in[2];
    const float* b1 = (const float*)d_in[3];
    const float* Wg = (const float*)d_in[4];
    const float* Wo = (const float*)d_in[5];
    const float* bo = (const float*)d_in[6];
    float* out = (float*)d_out;

    cudaFuncSetAttribute(gru_mma_kernel, cudaFuncAttributeMaxDynamicSharedMemorySize, SMEM_TOTAL);
    prep_kernel<<<160, 256>>>(xs, W1, b1, Wg);
    gru_mma_kernel<<<4096, 128, SMEM_TOTAL>>>(x, W1, Wo, bo, out);
}